// round 12
// baseline (speedup 1.0000x reference)
#include <cuda_runtime.h>
#include <cstdint>

// Problem constants
#define NB 16
#define NH 32
#define NG 8
#define ND 4096
#define DK 128
#define NM 8192
#define NM1 8193

// Output layout: y [16,4096] | Kc [16,8,8193,128] | Vc [16,8,8193,128]
static const long long KC_OFF = 65536LL;
static const long long VC_OFF = 65536LL + 16LL * 8 * 8193 * 128; // 134299648

// Packed f32x2 helpers (sm_103a)
__device__ __forceinline__ unsigned long long pack2(float lo, float hi) {
    unsigned long long r;
    asm("mov.b64 %0, {%1, %2};" : "=l"(r) : "f"(lo), "f"(hi));
    return r;
}
__device__ __forceinline__ unsigned long long fma2(unsigned long long a,
                                                   unsigned long long b,
                                                   unsigned long long c) {
    unsigned long long d;
    asm("fma.rn.f32x2 %0, %1, %2, %3;" : "=l"(d) : "l"(a), "l"(b), "l"(c));
    return d;
}
__device__ __forceinline__ float hadd2(unsigned long long p) {
    float lo, hi;
    asm("mov.b64 {%0, %1}, %2;" : "=f"(lo), "=f"(hi) : "l"(p));
    return lo + hi;
}

// Scratch (device globals — no allocations allowed)
__device__ float g_proj_part[16 * 16 * 48 * 128];
__device__ float g_proj[16 * 48 * 128];   // n<32: q[h], 32..39: k_new[g], 40..47: v_new[g]
__device__ float g_part[128 * 64 * 512];  // per-(b,g,chunk) partial o (4 heads x 128 v)
__device__ float g_stats[128 * 64 * 4];   // per-(b,g,chunk,head) sum of exp(l)
__device__ float g_o[16 * 32 * 128];
__device__ float g_ypart[32 * 16 * 4096];
__device__ unsigned int g_tick_n[48];     // tickets (reset by finishers -> replay-safe)
__device__ unsigned int g_tick_bg[128];
__device__ unsigned int g_tick_y[32];

// ---------------------------------------------------------------------------
// K1: projections (q/k_new/v_new), split over D into 16 chunks of 256.
// grid (48, 16) block 128, packed f32x2 FMA, d-loop unrolled x8 so ptxas
// front-batches the weight LDGs (raises MLP ~4 -> ~16+).
// Last chunk-block per n reduces + appends cache rows.
// ---------------------------------------------------------------------------
__global__ void k_proj(const float* __restrict__ x,
                       const float* __restrict__ Wq,
                       const float* __restrict__ Wk,
                       const float* __restrict__ Wv,
                       float* __restrict__ out) {
    int n = blockIdx.x;
    int c = blockIdx.y;
    int tid = threadIdx.x;
    int d0 = c * 256;
    const float* W = (n < 32) ? (Wq + (size_t)n * ND * DK)
                   : (n < 40) ? (Wk + (size_t)(n - 32) * ND * DK)
                              : (Wv + (size_t)(n - 40) * ND * DK);
    __shared__ __align__(16) float xs[16 * 256];
    for (int idx = tid; idx < 16 * 256; idx += 128) {
        int b = idx >> 8, d = idx & 255;
        xs[idx] = x[b * ND + d0 + d];
    }
    __syncthreads();
    unsigned long long accp[16];
#pragma unroll
    for (int b = 0; b < 16; b++) accp[b] = 0ull;
#pragma unroll 8
    for (int d = 0; d < 256; d += 4) {
        float w0 = W[(size_t)(d0 + d + 0) * DK + tid];
        float w1 = W[(size_t)(d0 + d + 1) * DK + tid];
        float w2 = W[(size_t)(d0 + d + 2) * DK + tid];
        float w3 = W[(size_t)(d0 + d + 3) * DK + tid];
        unsigned long long wp01 = pack2(w0, w1);
        unsigned long long wp23 = pack2(w2, w3);
#pragma unroll
        for (int b = 0; b < 16; b++) {
            unsigned long long x01 = *(const unsigned long long*)&xs[b * 256 + d];
            unsigned long long x23 = *(const unsigned long long*)&xs[b * 256 + d + 2];
            accp[b] = fma2(x01, wp01, accp[b]);
            accp[b] = fma2(x23, wp23, accp[b]);
        }
    }
#pragma unroll
    for (int b = 0; b < 16; b++)
        g_proj_part[((c * 16 + b) * 48 + n) * 128 + tid] = hadd2(accp[b]);

    // ---- ticket (writes -> fence -> SYNC -> atomic): last block reduces ----
    __threadfence();
    __syncthreads();
    __shared__ unsigned int isLast;
    if (tid == 0) isLast = (atomicAdd(&g_tick_n[n], 1) == 15);
    __syncthreads();
    if (!isLast) return;
    if (tid == 0) g_tick_n[n] = 0;
    for (int b = 0; b < 16; b++) {
        float s = 0.f;
#pragma unroll
        for (int cc = 0; cc < 16; cc++)
            s += __ldcg(&g_proj_part[((cc * 16 + b) * 48 + n) * 128 + tid]);
        g_proj[(b * 48 + n) * 128 + tid] = s;
        if (n >= 32 && n < 40)
            out[KC_OFF + ((long long)(b * 8 + n - 32) * NM1 + NM) * 128 + tid] = s;
        else if (n >= 40)
            out[VC_OFF + ((long long)(b * 8 + n - 40) * NM1 + NM) * 128 + tid] = s;
    }
}

// ---------------------------------------------------------------------------
// K2 (fused, R5 version): single pass per (b,g,chunk): stream K&V -> Kc/Vc,
// logits via warp reduce, e = exp(logit) (bounded logits), accumulate s and
// e*V. Depth-1 software prefetch. Last chunk-block per (b,g) combines -> g_o.
// ---------------------------------------------------------------------------
__global__ void __launch_bounds__(256, 3)
k_fused(const float* __restrict__ prevK,
        const float* __restrict__ prevV,
        float* __restrict__ out) {
    int bg = blockIdx.x >> 6;
    int chunk = blockIdx.x & 63;
    int b = bg >> 3, g = bg & 7;
    int tid = threadIdx.x, warp = tid >> 5, lane = tid & 31;
    int m0 = chunk * 128;

    float4 q0 = *(const float4*)&g_proj[(b * 48 + 0 * 8 + g) * 128 + lane * 4];
    float4 q1 = *(const float4*)&g_proj[(b * 48 + 1 * 8 + g) * 128 + lane * 4];
    float4 q2 = *(const float4*)&g_proj[(b * 48 + 2 * 8 + g) * 128 + lane * 4];
    float4 q3 = *(const float4*)&g_proj[(b * 48 + 3 * 8 + g) * 128 + lane * 4];

    const float4* srcK = (const float4*)(prevK + ((size_t)bg * NM + m0) * 128);
    const float4* srcV = (const float4*)(prevV + ((size_t)bg * NM + m0) * 128);
    float4* dstK = (float4*)(out + KC_OFF + ((long long)bg * NM1 + m0) * 128);
    float4* dstV = (float4*)(out + VC_OFF + ((long long)bg * NM1 + m0) * 128);

    float4 a0 = {0, 0, 0, 0}, a1 = a0, a2 = a0, a3 = a0;
    float s0 = 0.f, s1 = 0.f, s2 = 0.f, s3 = 0.f;

    int r = warp;
    float4 kv = __ldcs(srcK + r * 32 + lane);
    float4 vv = __ldcs(srcV + r * 32 + lane);
#pragma unroll
    for (int it = 0; it < 16; it++) {
        float4 kn = {0, 0, 0, 0}, vn = {0, 0, 0, 0};
        if (it < 15) {                        // prefetch next row
            kn = __ldcs(srcK + (r + 8) * 32 + lane);
            vn = __ldcs(srcV + (r + 8) * 32 + lane);
        }
        __stcs(dstK + r * 32 + lane, kv);
        __stcs(dstV + r * 32 + lane, vv);
        float l0 = kv.x * q0.x + kv.y * q0.y + kv.z * q0.z + kv.w * q0.w;
        float l1 = kv.x * q1.x + kv.y * q1.y + kv.z * q1.z + kv.w * q1.w;
        float l2 = kv.x * q2.x + kv.y * q2.y + kv.z * q2.z + kv.w * q2.w;
        float l3 = kv.x * q3.x + kv.y * q3.y + kv.z * q3.z + kv.w * q3.w;
#pragma unroll
        for (int off = 16; off > 0; off >>= 1) {
            l0 += __shfl_xor_sync(0xffffffffu, l0, off);
            l1 += __shfl_xor_sync(0xffffffffu, l1, off);
            l2 += __shfl_xor_sync(0xffffffffu, l2, off);
            l3 += __shfl_xor_sync(0xffffffffu, l3, off);
        }
        float e0 = __expf(l0), e1 = __expf(l1), e2 = __expf(l2), e3 = __expf(l3);
        s0 += e0; s1 += e1; s2 += e2; s3 += e3;
        a0.x += e0 * vv.x; a0.y += e0 * vv.y; a0.z += e0 * vv.z; a0.w += e0 * vv.w;
        a1.x += e1 * vv.x; a1.y += e1 * vv.y; a1.z += e1 * vv.z; a1.w += e1 * vv.w;
        a2.x += e2 * vv.x; a2.y += e2 * vv.y; a2.z += e2 * vv.z; a2.w += e2 * vv.w;
        a3.x += e3 * vv.x; a3.y += e3 * vv.y; a3.z += e3 * vv.z; a3.w += e3 * vv.w;
        kv = kn; vv = vn; r += 8;
    }

    // Block-level merge of 8 warp partials
    __shared__ __align__(16) float accs[8 * 512];
    __shared__ float ssum[8 * 4];
    float4* ap = (float4*)&accs[warp * 512];
    ap[lane] = a0; ap[32 + lane] = a1; ap[64 + lane] = a2; ap[96 + lane] = a3;
    if (lane == 0) {
        ssum[warp * 4 + 0] = s0; ssum[warp * 4 + 1] = s1;
        ssum[warp * 4 + 2] = s2; ssum[warp * 4 + 3] = s3;
    }
    __syncthreads();
    size_t pbase = ((size_t)bg * 64 + chunk) * 512;
    for (int idx = tid; idx < 512; idx += 256) {
        float s = 0.f;
#pragma unroll
        for (int w = 0; w < 8; w++) s += accs[w * 512 + idx];
        g_part[pbase + idx] = s;
    }
    if (tid < 4) {
        float t = 0.f;
#pragma unroll
        for (int w = 0; w < 8; w++) t += ssum[w * 4 + tid];
        g_stats[((size_t)bg * 64 + chunk) * 4 + tid] = t;
    }

    // ---- ticket (writes -> fence -> SYNC -> atomic): last block combines ----
    __threadfence();
    __syncthreads();
    __shared__ unsigned int isLast;
    if (tid == 0) isLast = (atomicAdd(&g_tick_bg[bg], 1) == 63);
    __syncthreads();
    if (!isLast) return;
    if (tid == 0) g_tick_bg[bg] = 0;

    __shared__ float s_en[4], s_den[4];
    if (warp < 4) {   // new-token logit per head ri = warp
        float4 qq = *(const float4*)&g_proj[(b * 48 + warp * 8 + g) * 128 + lane * 4];
        float4 kk = *(const float4*)&g_proj[(b * 48 + 32 + g) * 128 + lane * 4];
        float p = qq.x * kk.x + qq.y * kk.y + qq.z * kk.z + qq.w * kk.w;
#pragma unroll
        for (int off = 16; off > 0; off >>= 1)
            p += __shfl_xor_sync(0xffffffffu, p, off);
        if (lane == 0) s_en[warp] = __expf(p);
    }
    __syncthreads();
    if (tid < 4) {
        float den = s_en[tid];
#pragma unroll 8
        for (int c2 = 0; c2 < 64; c2++)
            den += __ldcg(&g_stats[((size_t)bg * 64 + c2) * 4 + tid]);
        s_den[tid] = den;
    }
    __syncthreads();
    for (int idx = tid; idx < 512; idx += 256) {
        int ri = idx >> 7, v = idx & 127;
        float acc = s_en[ri] * g_proj[(b * 48 + 40 + g) * 128 + v];
        size_t base = (size_t)bg * 64 * 512 + idx;
#pragma unroll 8
        for (int c2 = 0; c2 < 64; c2++)
            acc += __ldcg(&g_part[base + (size_t)c2 * 512]);
        g_o[(b * 32 + ri * 8 + g) * 128 + v] = acc / s_den[ri];
    }
}

// ---------------------------------------------------------------------------
// K3: y[b,d] = sum_hv o[b,hv] * Wo[hv,d]. grid (32,16), block 256 = 2 halves
// x 128 d, j-loop unrolled x8 for MLP. Last block per d0 reduces + writes y.
// ---------------------------------------------------------------------------
__global__ void k_y(const float* __restrict__ Wo, float* __restrict__ out) {
    int d0 = blockIdx.x * 128;
    int c = blockIdx.y;
    int tid = threadIdx.x;
    int half = tid >> 7;
    int dd = tid & 127;
    int hv0 = c * 256 + half * 128;
    __shared__ __align__(16) float os[2 * 16 * 128];
    for (int idx = tid; idx < 2 * 16 * 128; idx += 256) {
        int hh = idx >> 11, rem = idx & 2047;
        int b = rem >> 7, j = rem & 127;
        os[idx] = g_o[b * 4096 + c * 256 + hh * 128 + j];
    }
    __syncthreads();
    const float* oh = os + half * 2048;
    unsigned long long accp[16];
#pragma unroll
    for (int b = 0; b < 16; b++) accp[b] = 0ull;
#pragma unroll 8
    for (int j = 0; j < 128; j += 4) {
        float w0 = Wo[(size_t)(hv0 + j + 0) * 4096 + d0 + dd];
        float w1 = Wo[(size_t)(hv0 + j + 1) * 4096 + d0 + dd];
        float w2 = Wo[(size_t)(hv0 + j + 2) * 4096 + d0 + dd];
        float w3 = Wo[(size_t)(hv0 + j + 3) * 4096 + d0 + dd];
        unsigned long long wp01 = pack2(w0, w1);
        unsigned long long wp23 = pack2(w2, w3);
#pragma unroll
        for (int b = 0; b < 16; b++) {
            unsigned long long o01 = *(const unsigned long long*)&oh[b * 128 + j];
            unsigned long long o23 = *(const unsigned long long*)&oh[b * 128 + j + 2];
            accp[b] = fma2(o01, wp01, accp[b]);
            accp[b] = fma2(o23, wp23, accp[b]);
        }
    }
    int cc_out = c * 2 + half;
#pragma unroll
    for (int b = 0; b < 16; b++)
        g_ypart[(cc_out * 16 + b) * 4096 + d0 + dd] = hadd2(accp[b]);

    // ---- ticket (writes -> fence -> SYNC -> atomic): last block writes y ----
    __threadfence();
    __syncthreads();
    __shared__ unsigned int isLast;
    if (tid == 0) isLast = (atomicAdd(&g_tick_y[blockIdx.x], 1) == 15);
    __syncthreads();
    if (!isLast) return;
    if (tid == 0) g_tick_y[blockIdx.x] = 0;
    if (tid < 128) {
        for (int b = 0; b < 16; b++) {
            float s = 0.f;
#pragma unroll
            for (int cc = 0; cc < 32; cc++)
                s += __ldcg(&g_ypart[(cc * 16 + b) * 4096 + d0 + tid]);
            out[b * ND + d0 + tid] = s;
        }
    }
}

extern "C" void kernel_launch(void* const* d_in, const int* in_sizes, int n_in,
                              void* d_out, int out_size) {
    const float* x     = (const float*)d_in[0];
    const float* prevK = (const float*)d_in[1];
    const float* prevV = (const float*)d_in[2];
    const float* Wq    = (const float*)d_in[3];
    const float* Wk    = (const float*)d_in[4];
    const float* Wv    = (const float*)d_in[5];
    const float* Wo    = (const float*)d_in[6];
    float* out = (float*)d_out;

    k_proj<<<dim3(48, 16), 128>>>(x, Wq, Wk, Wv, out);
    k_fused<<<128 * 64, 256>>>(prevK, prevV, out);
    k_y<<<dim3(32, 16), 256>>>(Wo, out);
}

// round 13
// speedup vs baseline: 1.0044x; 1.0044x over previous
#include <cuda_runtime.h>
#include <cstdint>

// Problem constants
#define NB 16
#define NH 32
#define NG 8
#define ND 4096
#define DK 128
#define NM 8192
#define NM1 8193

// Output layout: y [16,4096] | Kc [16,8,8193,128] | Vc [16,8,8193,128]
static const long long KC_OFF = 65536LL;
static const long long VC_OFF = 65536LL + 16LL * 8 * 8193 * 128; // 134299648

// Packed f32x2 helpers (sm_103a)
__device__ __forceinline__ unsigned long long pack2(float lo, float hi) {
    unsigned long long r;
    asm("mov.b64 %0, {%1, %2};" : "=l"(r) : "f"(lo), "f"(hi));
    return r;
}
__device__ __forceinline__ unsigned long long fma2(unsigned long long a,
                                                   unsigned long long b,
                                                   unsigned long long c) {
    unsigned long long d;
    asm("fma.rn.f32x2 %0, %1, %2, %3;" : "=l"(d) : "l"(a), "l"(b), "l"(c));
    return d;
}
__device__ __forceinline__ float hadd2(unsigned long long p) {
    float lo, hi;
    asm("mov.b64 {%0, %1}, %2;" : "=f"(lo), "=f"(hi) : "l"(p));
    return lo + hi;
}

// Scratch (device globals — no allocations allowed)
__device__ float g_proj_part[16 * 16 * 48 * 128];
__device__ float g_proj[16 * 48 * 128];   // n<32: q[h], 32..39: k_new[g], 40..47: v_new[g]
__device__ float g_part[128 * 64 * 512];  // per-(b,g,chunk) partial o (4 heads x 128 v)
__device__ float g_stats[128 * 64 * 4];   // per-(b,g,chunk,head) sum of exp(l)
__device__ float g_o[16 * 32 * 128];
__device__ float g_ypart[32 * 16 * 4096];
__device__ unsigned int g_tick_n[48];     // tickets (reset by finishers -> replay-safe)
__device__ unsigned int g_tick_bg[128];
__device__ unsigned int g_tick_y[32];

// ---------------------------------------------------------------------------
// K1: projections (q/k_new/v_new), split over D into 16 chunks of 256.
// grid (48, 16) block 128, packed f32x2 FMA, d-loop unrolled x16 so ptxas
// front-batches the weight LDGs (confirmed win at x8: 56.6 -> 47.4us).
// Last chunk-block per n reduces + appends cache rows.
// ---------------------------------------------------------------------------
__global__ void k_proj(const float* __restrict__ x,
                       const float* __restrict__ Wq,
                       const float* __restrict__ Wk,
                       const float* __restrict__ Wv,
                       float* __restrict__ out) {
    int n = blockIdx.x;
    int c = blockIdx.y;
    int tid = threadIdx.x;
    int d0 = c * 256;
    const float* W = (n < 32) ? (Wq + (size_t)n * ND * DK)
                   : (n < 40) ? (Wk + (size_t)(n - 32) * ND * DK)
                              : (Wv + (size_t)(n - 40) * ND * DK);
    __shared__ __align__(16) float xs[16 * 256];
    for (int idx = tid; idx < 16 * 256; idx += 128) {
        int b = idx >> 8, d = idx & 255;
        xs[idx] = x[b * ND + d0 + d];
    }
    __syncthreads();
    unsigned long long accp[16];
#pragma unroll
    for (int b = 0; b < 16; b++) accp[b] = 0ull;
#pragma unroll 16
    for (int d = 0; d < 256; d += 4) {
        float w0 = W[(size_t)(d0 + d + 0) * DK + tid];
        float w1 = W[(size_t)(d0 + d + 1) * DK + tid];
        float w2 = W[(size_t)(d0 + d + 2) * DK + tid];
        float w3 = W[(size_t)(d0 + d + 3) * DK + tid];
        unsigned long long wp01 = pack2(w0, w1);
        unsigned long long wp23 = pack2(w2, w3);
#pragma unroll
        for (int b = 0; b < 16; b++) {
            unsigned long long x01 = *(const unsigned long long*)&xs[b * 256 + d];
            unsigned long long x23 = *(const unsigned long long*)&xs[b * 256 + d + 2];
            accp[b] = fma2(x01, wp01, accp[b]);
            accp[b] = fma2(x23, wp23, accp[b]);
        }
    }
#pragma unroll
    for (int b = 0; b < 16; b++)
        g_proj_part[((c * 16 + b) * 48 + n) * 128 + tid] = hadd2(accp[b]);

    // ---- ticket (writes -> fence -> SYNC -> atomic): last block reduces ----
    __threadfence();
    __syncthreads();
    __shared__ unsigned int isLast;
    if (tid == 0) isLast = (atomicAdd(&g_tick_n[n], 1) == 15);
    __syncthreads();
    if (!isLast) return;
    if (tid == 0) g_tick_n[n] = 0;
    for (int b = 0; b < 16; b++) {
        float s = 0.f;
#pragma unroll
        for (int cc = 0; cc < 16; cc++)
            s += __ldcg(&g_proj_part[((cc * 16 + b) * 48 + n) * 128 + tid]);
        g_proj[(b * 48 + n) * 128 + tid] = s;
        if (n >= 32 && n < 40)
            out[KC_OFF + ((long long)(b * 8 + n - 32) * NM1 + NM) * 128 + tid] = s;
        else if (n >= 40)
            out[VC_OFF + ((long long)(b * 8 + n - 40) * NM1 + NM) * 128 + tid] = s;
    }
}

// ---------------------------------------------------------------------------
// K2 (fused, R5 version): single pass per (b,g,chunk): stream K&V -> Kc/Vc,
// logits via warp reduce, e = exp(logit) (bounded logits), accumulate s and
// e*V. Depth-1 software prefetch. Last chunk-block per (b,g) combines -> g_o.
// ---------------------------------------------------------------------------
__global__ void __launch_bounds__(256, 3)
k_fused(const float* __restrict__ prevK,
        const float* __restrict__ prevV,
        float* __restrict__ out) {
    int bg = blockIdx.x >> 6;
    int chunk = blockIdx.x & 63;
    int b = bg >> 3, g = bg & 7;
    int tid = threadIdx.x, warp = tid >> 5, lane = tid & 31;
    int m0 = chunk * 128;

    float4 q0 = *(const float4*)&g_proj[(b * 48 + 0 * 8 + g) * 128 + lane * 4];
    float4 q1 = *(const float4*)&g_proj[(b * 48 + 1 * 8 + g) * 128 + lane * 4];
    float4 q2 = *(const float4*)&g_proj[(b * 48 + 2 * 8 + g) * 128 + lane * 4];
    float4 q3 = *(const float4*)&g_proj[(b * 48 + 3 * 8 + g) * 128 + lane * 4];

    const float4* srcK = (const float4*)(prevK + ((size_t)bg * NM + m0) * 128);
    const float4* srcV = (const float4*)(prevV + ((size_t)bg * NM + m0) * 128);
    float4* dstK = (float4*)(out + KC_OFF + ((long long)bg * NM1 + m0) * 128);
    float4* dstV = (float4*)(out + VC_OFF + ((long long)bg * NM1 + m0) * 128);

    float4 a0 = {0, 0, 0, 0}, a1 = a0, a2 = a0, a3 = a0;
    float s0 = 0.f, s1 = 0.f, s2 = 0.f, s3 = 0.f;

    int r = warp;
    float4 kv = __ldcs(srcK + r * 32 + lane);
    float4 vv = __ldcs(srcV + r * 32 + lane);
#pragma unroll
    for (int it = 0; it < 16; it++) {
        float4 kn = {0, 0, 0, 0}, vn = {0, 0, 0, 0};
        if (it < 15) {                        // prefetch next row
            kn = __ldcs(srcK + (r + 8) * 32 + lane);
            vn = __ldcs(srcV + (r + 8) * 32 + lane);
        }
        __stcs(dstK + r * 32 + lane, kv);
        __stcs(dstV + r * 32 + lane, vv);
        float l0 = kv.x * q0.x + kv.y * q0.y + kv.z * q0.z + kv.w * q0.w;
        float l1 = kv.x * q1.x + kv.y * q1.y + kv.z * q1.z + kv.w * q1.w;
        float l2 = kv.x * q2.x + kv.y * q2.y + kv.z * q2.z + kv.w * q2.w;
        float l3 = kv.x * q3.x + kv.y * q3.y + kv.z * q3.z + kv.w * q3.w;
#pragma unroll
        for (int off = 16; off > 0; off >>= 1) {
            l0 += __shfl_xor_sync(0xffffffffu, l0, off);
            l1 += __shfl_xor_sync(0xffffffffu, l1, off);
            l2 += __shfl_xor_sync(0xffffffffu, l2, off);
            l3 += __shfl_xor_sync(0xffffffffu, l3, off);
        }
        float e0 = __expf(l0), e1 = __expf(l1), e2 = __expf(l2), e3 = __expf(l3);
        s0 += e0; s1 += e1; s2 += e2; s3 += e3;
        a0.x += e0 * vv.x; a0.y += e0 * vv.y; a0.z += e0 * vv.z; a0.w += e0 * vv.w;
        a1.x += e1 * vv.x; a1.y += e1 * vv.y; a1.z += e1 * vv.z; a1.w += e1 * vv.w;
        a2.x += e2 * vv.x; a2.y += e2 * vv.y; a2.z += e2 * vv.z; a2.w += e2 * vv.w;
        a3.x += e3 * vv.x; a3.y += e3 * vv.y; a3.z += e3 * vv.z; a3.w += e3 * vv.w;
        kv = kn; vv = vn; r += 8;
    }

    // Block-level merge of 8 warp partials
    __shared__ __align__(16) float accs[8 * 512];
    __shared__ float ssum[8 * 4];
    float4* ap = (float4*)&accs[warp * 512];
    ap[lane] = a0; ap[32 + lane] = a1; ap[64 + lane] = a2; ap[96 + lane] = a3;
    if (lane == 0) {
        ssum[warp * 4 + 0] = s0; ssum[warp * 4 + 1] = s1;
        ssum[warp * 4 + 2] = s2; ssum[warp * 4 + 3] = s3;
    }
    __syncthreads();
    size_t pbase = ((size_t)bg * 64 + chunk) * 512;
    for (int idx = tid; idx < 512; idx += 256) {
        float s = 0.f;
#pragma unroll
        for (int w = 0; w < 8; w++) s += accs[w * 512 + idx];
        g_part[pbase + idx] = s;
    }
    if (tid < 4) {
        float t = 0.f;
#pragma unroll
        for (int w = 0; w < 8; w++) t += ssum[w * 4 + tid];
        g_stats[((size_t)bg * 64 + chunk) * 4 + tid] = t;
    }

    // ---- ticket (writes -> fence -> SYNC -> atomic): last block combines ----
    __threadfence();
    __syncthreads();
    __shared__ unsigned int isLast;
    if (tid == 0) isLast = (atomicAdd(&g_tick_bg[bg], 1) == 63);
    __syncthreads();
    if (!isLast) return;
    if (tid == 0) g_tick_bg[bg] = 0;

    __shared__ float s_en[4], s_den[4];
    if (warp < 4) {   // new-token logit per head ri = warp
        float4 qq = *(const float4*)&g_proj[(b * 48 + warp * 8 + g) * 128 + lane * 4];
        float4 kk = *(const float4*)&g_proj[(b * 48 + 32 + g) * 128 + lane * 4];
        float p = qq.x * kk.x + qq.y * kk.y + qq.z * kk.z + qq.w * kk.w;
#pragma unroll
        for (int off = 16; off > 0; off >>= 1)
            p += __shfl_xor_sync(0xffffffffu, p, off);
        if (lane == 0) s_en[warp] = __expf(p);
    }
    __syncthreads();
    if (tid < 4) {
        float den = s_en[tid];
#pragma unroll 8
        for (int c2 = 0; c2 < 64; c2++)
            den += __ldcg(&g_stats[((size_t)bg * 64 + c2) * 4 + tid]);
        s_den[tid] = den;
    }
    __syncthreads();
    for (int idx = tid; idx < 512; idx += 256) {
        int ri = idx >> 7, v = idx & 127;
        float acc = s_en[ri] * g_proj[(b * 48 + 40 + g) * 128 + v];
        size_t base = (size_t)bg * 64 * 512 + idx;
#pragma unroll 8
        for (int c2 = 0; c2 < 64; c2++)
            acc += __ldcg(&g_part[base + (size_t)c2 * 512]);
        g_o[(b * 32 + ri * 8 + g) * 128 + v] = acc / s_den[ri];
    }
}

// ---------------------------------------------------------------------------
// K3: y[b,d] = sum_hv o[b,hv] * Wo[hv,d]. grid (32,16), block 256 = 2 halves
// x 128 d (R11 form, no j-loop unroll pragma — unroll 8 regressed in R12).
// Last block per d0 reduces and writes y.
// ---------------------------------------------------------------------------
__global__ void k_y(const float* __restrict__ Wo, float* __restrict__ out) {
    int d0 = blockIdx.x * 128;
    int c = blockIdx.y;
    int tid = threadIdx.x;
    int half = tid >> 7;
    int dd = tid & 127;
    int hv0 = c * 256 + half * 128;
    __shared__ __align__(16) float os[2 * 16 * 128];
    for (int idx = tid; idx < 2 * 16 * 128; idx += 256) {
        int hh = idx >> 11, rem = idx & 2047;
        int b = rem >> 7, j = rem & 127;
        os[idx] = g_o[b * 4096 + c * 256 + hh * 128 + j];
    }
    __syncthreads();
    const float* oh = os + half * 2048;
    unsigned long long accp[16];
#pragma unroll
    for (int b = 0; b < 16; b++) accp[b] = 0ull;
    for (int j = 0; j < 128; j += 4) {
        float w0 = Wo[(size_t)(hv0 + j + 0) * 4096 + d0 + dd];
        float w1 = Wo[(size_t)(hv0 + j + 1) * 4096 + d0 + dd];
        float w2 = Wo[(size_t)(hv0 + j + 2) * 4096 + d0 + dd];
        float w3 = Wo[(size_t)(hv0 + j + 3) * 4096 + d0 + dd];
        unsigned long long wp01 = pack2(w0, w1);
        unsigned long long wp23 = pack2(w2, w3);
#pragma unroll
        for (int b = 0; b < 16; b++) {
            unsigned long long o01 = *(const unsigned long long*)&oh[b * 128 + j];
            unsigned long long o23 = *(const unsigned long long*)&oh[b * 128 + j + 2];
            accp[b] = fma2(o01, wp01, accp[b]);
            accp[b] = fma2(o23, wp23, accp[b]);
        }
    }
    int cc_out = c * 2 + half;
#pragma unroll
    for (int b = 0; b < 16; b++)
        g_ypart[(cc_out * 16 + b) * 4096 + d0 + dd] = hadd2(accp[b]);

    // ---- ticket (writes -> fence -> SYNC -> atomic): last block writes y ----
    __threadfence();
    __syncthreads();
    __shared__ unsigned int isLast;
    if (tid == 0) isLast = (atomicAdd(&g_tick_y[blockIdx.x], 1) == 15);
    __syncthreads();
    if (!isLast) return;
    if (tid == 0) g_tick_y[blockIdx.x] = 0;
    if (tid < 128) {
        for (int b = 0; b < 16; b++) {
            float s = 0.f;
#pragma unroll
            for (int cc = 0; cc < 32; cc++)
                s += __ldcg(&g_ypart[(cc * 16 + b) * 4096 + d0 + tid]);
            out[b * ND + d0 + tid] = s;
        }
    }
}

extern "C" void kernel_launch(void* const* d_in, const int* in_sizes, int n_in,
                              void* d_out, int out_size) {
    const float* x     = (const float*)d_in[0];
    const float* prevK = (const float*)d_in[1];
    const float* prevV = (const float*)d_in[2];
    const float* Wq    = (const float*)d_in[3];
    const float* Wk    = (const float*)d_in[4];
    const float* Wv    = (const float*)d_in[5];
    const float* Wo    = (const float*)d_in[6];
    float* out = (float*)d_out;

    k_proj<<<dim3(48, 16), 128>>>(x, Wq, Wk, Wv, out);
    k_fused<<<128 * 64, 256>>>(prevK, prevV, out);
    k_y<<<dim3(32, 16), 256>>>(Wo, out);
}

// round 14
// speedup vs baseline: 1.0339x; 1.0294x over previous
#include <cuda_runtime.h>
#include <cstdint>

// Problem constants
#define NB 16
#define NH 32
#define NG 8
#define ND 4096
#define DK 128
#define NM 8192
#define NM1 8193

// Output layout: y [16,4096] | Kc [16,8,8193,128] | Vc [16,8,8193,128]
static const long long KC_OFF = 65536LL;
static const long long VC_OFF = 65536LL + 16LL * 8 * 8193 * 128; // 134299648

// Packed f32x2 helpers (sm_103a)
__device__ __forceinline__ unsigned long long pack2(float lo, float hi) {
    unsigned long long r;
    asm("mov.b64 %0, {%1, %2};" : "=l"(r) : "f"(lo), "f"(hi));
    return r;
}
__device__ __forceinline__ unsigned long long fma2(unsigned long long a,
                                                   unsigned long long b,
                                                   unsigned long long c) {
    unsigned long long d;
    asm("fma.rn.f32x2 %0, %1, %2, %3;" : "=l"(d) : "l"(a), "l"(b), "l"(c));
    return d;
}
__device__ __forceinline__ float hadd2(unsigned long long p) {
    float lo, hi;
    asm("mov.b64 {%0, %1}, %2;" : "=f"(lo), "=f"(hi) : "l"(p));
    return lo + hi;
}

// Scratch (device globals — no allocations allowed)
__device__ float g_proj_part[16 * 16 * 48 * 128];
__device__ float g_proj[16 * 48 * 128];   // n<32: q[h], 32..39: k_new[g], 40..47: v_new[g]
__device__ float g_part[128 * 64 * 512];  // per-(b,g,chunk) partial o (4 heads x 128 v)
__device__ float g_stats[128 * 64 * 4];   // per-(b,g,chunk,head) sum of exp(l)
__device__ float g_o[16 * 32 * 128];
__device__ float g_ypart[32 * 16 * 4096];
__device__ unsigned int g_tick_n[48];     // tickets (reset by finishers -> replay-safe)
__device__ unsigned int g_tick_bg[128];
__device__ unsigned int g_tick_y[32];

// ---------------------------------------------------------------------------
// K1: projections (q/k_new/v_new), split over D into 16 chunks of 256.
// grid (48, 16) block 128, packed f32x2 FMA, d-loop unrolled x8 (measured
// best: 47.4us; x16 regressed to 55.6 — ptxas reg budget stops batching).
// Last chunk-block per n reduces + appends cache rows.
// ---------------------------------------------------------------------------
__global__ void k_proj(const float* __restrict__ x,
                       const float* __restrict__ Wq,
                       const float* __restrict__ Wk,
                       const float* __restrict__ Wv,
                       float* __restrict__ out) {
    int n = blockIdx.x;
    int c = blockIdx.y;
    int tid = threadIdx.x;
    int d0 = c * 256;
    const float* W = (n < 32) ? (Wq + (size_t)n * ND * DK)
                   : (n < 40) ? (Wk + (size_t)(n - 32) * ND * DK)
                              : (Wv + (size_t)(n - 40) * ND * DK);
    __shared__ __align__(16) float xs[16 * 256];
    for (int idx = tid; idx < 16 * 256; idx += 128) {
        int b = idx >> 8, d = idx & 255;
        xs[idx] = x[b * ND + d0 + d];
    }
    __syncthreads();
    unsigned long long accp[16];
#pragma unroll
    for (int b = 0; b < 16; b++) accp[b] = 0ull;
#pragma unroll 8
    for (int d = 0; d < 256; d += 4) {
        float w0 = W[(size_t)(d0 + d + 0) * DK + tid];
        float w1 = W[(size_t)(d0 + d + 1) * DK + tid];
        float w2 = W[(size_t)(d0 + d + 2) * DK + tid];
        float w3 = W[(size_t)(d0 + d + 3) * DK + tid];
        unsigned long long wp01 = pack2(w0, w1);
        unsigned long long wp23 = pack2(w2, w3);
#pragma unroll
        for (int b = 0; b < 16; b++) {
            unsigned long long x01 = *(const unsigned long long*)&xs[b * 256 + d];
            unsigned long long x23 = *(const unsigned long long*)&xs[b * 256 + d + 2];
            accp[b] = fma2(x01, wp01, accp[b]);
            accp[b] = fma2(x23, wp23, accp[b]);
        }
    }
#pragma unroll
    for (int b = 0; b < 16; b++)
        g_proj_part[((c * 16 + b) * 48 + n) * 128 + tid] = hadd2(accp[b]);

    // ---- ticket (writes -> fence -> SYNC -> atomic): last block reduces ----
    __threadfence();
    __syncthreads();
    __shared__ unsigned int isLast;
    if (tid == 0) isLast = (atomicAdd(&g_tick_n[n], 1) == 15);
    __syncthreads();
    if (!isLast) return;
    if (tid == 0) g_tick_n[n] = 0;
    for (int b = 0; b < 16; b++) {
        float s = 0.f;
#pragma unroll
        for (int cc = 0; cc < 16; cc++)
            s += __ldcg(&g_proj_part[((cc * 16 + b) * 48 + n) * 128 + tid]);
        g_proj[(b * 48 + n) * 128 + tid] = s;
        if (n >= 32 && n < 40)
            out[KC_OFF + ((long long)(b * 8 + n - 32) * NM1 + NM) * 128 + tid] = s;
        else if (n >= 40)
            out[VC_OFF + ((long long)(b * 8 + n - 40) * NM1 + NM) * 128 + tid] = s;
    }
}

// ---------------------------------------------------------------------------
// K2 (fused, R5 version): single pass per (b,g,chunk): stream K&V -> Kc/Vc,
// logits via warp reduce, e = exp(logit) (bounded logits), accumulate s and
// e*V. Depth-1 software prefetch. Last chunk-block per (b,g) combines -> g_o.
// ---------------------------------------------------------------------------
__global__ void __launch_bounds__(256, 3)
k_fused(const float* __restrict__ prevK,
        const float* __restrict__ prevV,
        float* __restrict__ out) {
    int bg = blockIdx.x >> 6;
    int chunk = blockIdx.x & 63;
    int b = bg >> 3, g = bg & 7;
    int tid = threadIdx.x, warp = tid >> 5, lane = tid & 31;
    int m0 = chunk * 128;

    float4 q0 = *(const float4*)&g_proj[(b * 48 + 0 * 8 + g) * 128 + lane * 4];
    float4 q1 = *(const float4*)&g_proj[(b * 48 + 1 * 8 + g) * 128 + lane * 4];
    float4 q2 = *(const float4*)&g_proj[(b * 48 + 2 * 8 + g) * 128 + lane * 4];
    float4 q3 = *(const float4*)&g_proj[(b * 48 + 3 * 8 + g) * 128 + lane * 4];

    const float4* srcK = (const float4*)(prevK + ((size_t)bg * NM + m0) * 128);
    const float4* srcV = (const float4*)(prevV + ((size_t)bg * NM + m0) * 128);
    float4* dstK = (float4*)(out + KC_OFF + ((long long)bg * NM1 + m0) * 128);
    float4* dstV = (float4*)(out + VC_OFF + ((long long)bg * NM1 + m0) * 128);

    float4 a0 = {0, 0, 0, 0}, a1 = a0, a2 = a0, a3 = a0;
    float s0 = 0.f, s1 = 0.f, s2 = 0.f, s3 = 0.f;

    int r = warp;
    float4 kv = __ldcs(srcK + r * 32 + lane);
    float4 vv = __ldcs(srcV + r * 32 + lane);
#pragma unroll
    for (int it = 0; it < 16; it++) {
        float4 kn = {0, 0, 0, 0}, vn = {0, 0, 0, 0};
        if (it < 15) {                        // prefetch next row
            kn = __ldcs(srcK + (r + 8) * 32 + lane);
            vn = __ldcs(srcV + (r + 8) * 32 + lane);
        }
        __stcs(dstK + r * 32 + lane, kv);
        __stcs(dstV + r * 32 + lane, vv);
        float l0 = kv.x * q0.x + kv.y * q0.y + kv.z * q0.z + kv.w * q0.w;
        float l1 = kv.x * q1.x + kv.y * q1.y + kv.z * q1.z + kv.w * q1.w;
        float l2 = kv.x * q2.x + kv.y * q2.y + kv.z * q2.z + kv.w * q2.w;
        float l3 = kv.x * q3.x + kv.y * q3.y + kv.z * q3.z + kv.w * q3.w;
#pragma unroll
        for (int off = 16; off > 0; off >>= 1) {
            l0 += __shfl_xor_sync(0xffffffffu, l0, off);
            l1 += __shfl_xor_sync(0xffffffffu, l1, off);
            l2 += __shfl_xor_sync(0xffffffffu, l2, off);
            l3 += __shfl_xor_sync(0xffffffffu, l3, off);
        }
        float e0 = __expf(l0), e1 = __expf(l1), e2 = __expf(l2), e3 = __expf(l3);
        s0 += e0; s1 += e1; s2 += e2; s3 += e3;
        a0.x += e0 * vv.x; a0.y += e0 * vv.y; a0.z += e0 * vv.z; a0.w += e0 * vv.w;
        a1.x += e1 * vv.x; a1.y += e1 * vv.y; a1.z += e1 * vv.z; a1.w += e1 * vv.w;
        a2.x += e2 * vv.x; a2.y += e2 * vv.y; a2.z += e2 * vv.z; a2.w += e2 * vv.w;
        a3.x += e3 * vv.x; a3.y += e3 * vv.y; a3.z += e3 * vv.z; a3.w += e3 * vv.w;
        kv = kn; vv = vn; r += 8;
    }

    // Block-level merge of 8 warp partials
    __shared__ __align__(16) float accs[8 * 512];
    __shared__ float ssum[8 * 4];
    float4* ap = (float4*)&accs[warp * 512];
    ap[lane] = a0; ap[32 + lane] = a1; ap[64 + lane] = a2; ap[96 + lane] = a3;
    if (lane == 0) {
        ssum[warp * 4 + 0] = s0; ssum[warp * 4 + 1] = s1;
        ssum[warp * 4 + 2] = s2; ssum[warp * 4 + 3] = s3;
    }
    __syncthreads();
    size_t pbase = ((size_t)bg * 64 + chunk) * 512;
    for (int idx = tid; idx < 512; idx += 256) {
        float s = 0.f;
#pragma unroll
        for (int w = 0; w < 8; w++) s += accs[w * 512 + idx];
        g_part[pbase + idx] = s;
    }
    if (tid < 4) {
        float t = 0.f;
#pragma unroll
        for (int w = 0; w < 8; w++) t += ssum[w * 4 + tid];
        g_stats[((size_t)bg * 64 + chunk) * 4 + tid] = t;
    }

    // ---- ticket (writes -> fence -> SYNC -> atomic): last block combines ----
    __threadfence();
    __syncthreads();
    __shared__ unsigned int isLast;
    if (tid == 0) isLast = (atomicAdd(&g_tick_bg[bg], 1) == 63);
    __syncthreads();
    if (!isLast) return;
    if (tid == 0) g_tick_bg[bg] = 0;

    __shared__ float s_en[4], s_den[4];
    if (warp < 4) {   // new-token logit per head ri = warp
        float4 qq = *(const float4*)&g_proj[(b * 48 + warp * 8 + g) * 128 + lane * 4];
        float4 kk = *(const float4*)&g_proj[(b * 48 + 32 + g) * 128 + lane * 4];
        float p = qq.x * kk.x + qq.y * kk.y + qq.z * kk.z + qq.w * kk.w;
#pragma unroll
        for (int off = 16; off > 0; off >>= 1)
            p += __shfl_xor_sync(0xffffffffu, p, off);
        if (lane == 0) s_en[warp] = __expf(p);
    }
    __syncthreads();
    if (tid < 4) {
        float den = s_en[tid];
#pragma unroll 8
        for (int c2 = 0; c2 < 64; c2++)
            den += __ldcg(&g_stats[((size_t)bg * 64 + c2) * 4 + tid]);
        s_den[tid] = den;
    }
    __syncthreads();
    for (int idx = tid; idx < 512; idx += 256) {
        int ri = idx >> 7, v = idx & 127;
        float acc = s_en[ri] * g_proj[(b * 48 + 40 + g) * 128 + v];
        size_t base = (size_t)bg * 64 * 512 + idx;
#pragma unroll 8
        for (int c2 = 0; c2 < 64; c2++)
            acc += __ldcg(&g_part[base + (size_t)c2 * 512]);
        g_o[(b * 32 + ri * 8 + g) * 128 + v] = acc / s_den[ri];
    }
}

// ---------------------------------------------------------------------------
// K3: y[b,d] = sum_hv o[b,hv] * Wo[hv,d]. grid (32,16), block 256 = 2 halves
// x 128 d (R11 form, no j-loop unroll pragma — unroll 8 regressed in R12).
// Last block per d0 reduces and writes y.
// ---------------------------------------------------------------------------
__global__ void k_y(const float* __restrict__ Wo, float* __restrict__ out) {
    int d0 = blockIdx.x * 128;
    int c = blockIdx.y;
    int tid = threadIdx.x;
    int half = tid >> 7;
    int dd = tid & 127;
    int hv0 = c * 256 + half * 128;
    __shared__ __align__(16) float os[2 * 16 * 128];
    for (int idx = tid; idx < 2 * 16 * 128; idx += 256) {
        int hh = idx >> 11, rem = idx & 2047;
        int b = rem >> 7, j = rem & 127;
        os[idx] = g_o[b * 4096 + c * 256 + hh * 128 + j];
    }
    __syncthreads();
    const float* oh = os + half * 2048;
    unsigned long long accp[16];
#pragma unroll
    for (int b = 0; b < 16; b++) accp[b] = 0ull;
    for (int j = 0; j < 128; j += 4) {
        float w0 = Wo[(size_t)(hv0 + j + 0) * 4096 + d0 + dd];
        float w1 = Wo[(size_t)(hv0 + j + 1) * 4096 + d0 + dd];
        float w2 = Wo[(size_t)(hv0 + j + 2) * 4096 + d0 + dd];
        float w3 = Wo[(size_t)(hv0 + j + 3) * 4096 + d0 + dd];
        unsigned long long wp01 = pack2(w0, w1);
        unsigned long long wp23 = pack2(w2, w3);
#pragma unroll
        for (int b = 0; b < 16; b++) {
            unsigned long long o01 = *(const unsigned long long*)&oh[b * 128 + j];
            unsigned long long o23 = *(const unsigned long long*)&oh[b * 128 + j + 2];
            accp[b] = fma2(o01, wp01, accp[b]);
            accp[b] = fma2(o23, wp23, accp[b]);
        }
    }
    int cc_out = c * 2 + half;
#pragma unroll
    for (int b = 0; b < 16; b++)
        g_ypart[(cc_out * 16 + b) * 4096 + d0 + dd] = hadd2(accp[b]);

    // ---- ticket (writes -> fence -> SYNC -> atomic): last block writes y ----
    __threadfence();
    __syncthreads();
    __shared__ unsigned int isLast;
    if (tid == 0) isLast = (atomicAdd(&g_tick_y[blockIdx.x], 1) == 15);
    __syncthreads();
    if (!isLast) return;
    if (tid == 0) g_tick_y[blockIdx.x] = 0;
    if (tid < 128) {
        for (int b = 0; b < 16; b++) {
            float s = 0.f;
#pragma unroll
            for (int cc = 0; cc < 32; cc++)
                s += __ldcg(&g_ypart[(cc * 16 + b) * 4096 + d0 + tid]);
            out[b * ND + d0 + tid] = s;
        }
    }
}

extern "C" void kernel_launch(void* const* d_in, const int* in_sizes, int n_in,
                              void* d_out, int out_size) {
    const float* x     = (const float*)d_in[0];
    const float* prevK = (const float*)d_in[1];
    const float* prevV = (const float*)d_in[2];
    const float* Wq    = (const float*)d_in[3];
    const float* Wk    = (const float*)d_in[4];
    const float* Wv    = (const float*)d_in[5];
    const float* Wo    = (const float*)d_in[6];
    float* out = (float*)d_out;

    k_proj<<<dim3(48, 16), 128>>>(x, Wq, Wk, Wv, out);
    k_fused<<<128 * 64, 256>>>(prevK, prevV, out);
    k_y<<<dim3(32, 16), 256>>>(Wo, out);
}